// round 12
// baseline (speedup 1.0000x reference)
#include <cuda_runtime.h>

// Problem constants (fixed by the dataset): B=4, R=16384, S=48, C=32
#define NS 48      // samples per ray
#define NC 32      // channels
#define NI 47      // intervals = NS-1
#define FULL 0xffffffffu

// Final form. One warp per ray, 4 warps/CTA (best-measured config across
// block sizes {64,128,256}, occupancy caps, smem/cp.async staging, and a
// persistent variant — all bracketed 66.1-67.1us; this one is the floor).
//
// Interval math parallelized across lanes:
//   lane l owns interval l (chunk A) and interval 32+l for l<15 (chunk B).
// Transmittance cumprod -> warp shuffle product scan.
// Color compositing rewritten as sum_s c_s * u_s, u_s = 0.5*(w_{s-1}+w_s).
// All 12 float4 color loads are issued UP FRONT so their DRAM latency is
// hidden under the softplus/scan/shuffle phase (MLP~12 per thread).
// Weight/depth stores are issued BEFORE the color-consumption FMA tail so
// the write stream drains under compute instead of bunching at warp exit.
//
// Depth clip note: reference clips composite_depth to [min(depths), max(depths)]
// over the WHOLE tensor. Per ray, d = sum(w*dmid)/sum(w) is a convex combination
// of midpoints strictly inside this ray's [dp0, dp_{NS-1}], which is inside the
// global range — so the clip is an identity whenever wsum > 0, which is
// guaranteed for this data. We clamp to the ray-local bounds, which yields the
// identical result without a global reduction.
__global__ void __launch_bounds__(128)
march_kernel(const float* __restrict__ colors,
             const float* __restrict__ densities,
             const float* __restrict__ depths,
             float* __restrict__ out_rgb,     // [n_rays, NC]
             float* __restrict__ out_depth,   // [n_rays]
             float* __restrict__ out_w,       // [n_rays, NI]
             int n_rays)
{
    const int warp = (blockIdx.x * blockDim.x + threadIdx.x) >> 5;
    const int lane = threadIdx.x & 31;
    if (warp >= n_rays) return;

    const size_t ray = (size_t)warp;
    const float* __restrict__ dn = densities + ray * NS;
    const float* __restrict__ dp = depths + ray * NS;

    // ---- scalar samples first (needed soonest)
    float denA = __ldg(dn + lane);
    float depA = __ldg(dp + lane);
    float denB = 0.0f, depB = 0.0f;
    if (lane < 16) {
        denB = __ldg(dn + 32 + lane);
        depB = __ldg(dp + 32 + lane);
    }

    // ---- issue ALL color loads now; consumed only after the scan phase.
    // lane -> (sample group g = lane>>3, channel block c4 = lane&7);
    // batch k covers sample s = 4k+g.
    const int g  = lane >> 3;
    const int c4 = lane & 7;
    const float4* __restrict__ cp = (const float4*)(colors + ray * (NS * NC));
    float4 c[12];
    #pragma unroll
    for (int k = 0; k < 12; k++)
        c[k] = __ldg(&cp[(4 * k + g) * 8 + c4]);

    // ---- neighbor (sample s+1) values
    float denA1 = __shfl_down_sync(FULL, denA, 1);   // sample lane+1 (lane<31)
    float depA1 = __shfl_down_sync(FULL, depA, 1);
    float denB0 = __shfl_sync(FULL, denB, 0);        // sample 32
    float depB0 = __shfl_sync(FULL, depB, 0);
    if (lane == 31) { denA1 = denB0; depA1 = depB0; }
    float denB1 = __shfl_down_sync(FULL, denB, 1);   // sample 33+lane (lane<15)
    float depB1 = __shfl_down_sync(FULL, depB, 1);

    // ray-local depth bounds (sorted): dp0 = sample 0, dpN = sample NS-1
    float dp0 = __shfl_sync(FULL, depA, 0);
    float dpN = __shfl_sync(FULL, depB, 15);

    // ---- per-interval alpha / v  (chunk A: i = lane, valid since NI=47>31)
    float deltaA = depA1 - depA;
    float dmidA  = 0.5f * (depA1 + depA);
    float smidA  = 0.5f * (denA1 + denA) - 1.0f;
    float spA    = log1pf(expf(smidA));
    float alphaA = 1.0f - expf(-spA * deltaA);
    float vA     = 1.0f - alphaA + 1e-10f;

    // chunk B: i = 32+lane, valid for lane < 15
    float alphaB = 0.0f, dmidB = 0.0f, vB = 1.0f;
    if (lane < 15) {
        float deltaB = depB1 - depB;
        dmidB  = 0.5f * (depB1 + depB);
        float smidB = 0.5f * (denB1 + denB) - 1.0f;
        float spB   = log1pf(expf(smidB));
        alphaB = 1.0f - expf(-spB * deltaB);
        vB     = 1.0f - alphaB + 1e-10f;
    }

    // ---- inclusive product scan of vA (full 32 lanes)
    float p = vA;
    #pragma unroll
    for (int off = 1; off < 32; off <<= 1) {
        float t = __shfl_up_sync(FULL, p, off);
        if (lane >= off) p *= t;
    }
    float TexA = __shfl_up_sync(FULL, p, 1);
    if (lane == 0) TexA = 1.0f;
    float wA = alphaA * TexA;
    float TtotA = __shfl_sync(FULL, p, 31);

    // ---- scan of vB: only prefixes over 15 elements are consumed,
    // so 4 steps (off=1,2,4,8) suffice.
    float q = vB;
    #pragma unroll
    for (int off = 1; off < 16; off <<= 1) {
        float t = __shfl_up_sync(FULL, q, off);
        if (lane >= off) q *= t;
    }
    float TexB = __shfl_up_sync(FULL, q, 1);
    if (lane == 0) TexB = 1.0f;
    float wB = alphaB * (TtotA * TexB);   // zero for lane >= 15

    // ---- EARLY stores: weights are final now; let the write stream drain
    // under the remaining compute instead of bunching at warp exit.
    out_w[ray * NI + lane] = wA;                     // i = 0..31
    if (lane < 15)
        out_w[ray * NI + 32 + lane] = wB;            // i = 32..46

    // ---- wsum / dsum reductions (butterfly)
    float wsum = wA + wB;
    float dsum = wA * dmidA + wB * dmidB;
    #pragma unroll
    for (int off = 16; off >= 1; off >>= 1) {
        wsum += __shfl_xor_sync(FULL, wsum, off);
        dsum += __shfl_xor_sync(FULL, dsum, off);
    }

    if (lane == 0) {
        float d = dsum / wsum;
        // wsum > 0 is guaranteed for this data; clamp to ray-local bounds,
        // which equals the reference's global clip (see comment above).
        if (!(d == d)) d = dpN;                      // defensive nan -> upper bound
        d = fminf(d, dpN);
        d = fmaxf(d, dp0);
        out_depth[ray] = d;
    }

    // ---- u_s = 0.5*(w_{s-1} + w_s)
    float wAm1 = __shfl_up_sync(FULL, wA, 1);        // w_{lane-1}
    if (lane == 0) wAm1 = 0.0f;
    float uA = 0.5f * (wAm1 + wA);                   // s = lane (0..31)
    float wBm1 = __shfl_up_sync(FULL, wB, 1);        // w_{31+lane} for lane>=1
    float wA31 = __shfl_sync(FULL, wA, 31);
    if (lane == 0) wBm1 = wA31;                      // w_31
    float uB = 0.5f * (wBm1 + wB);                   // s = 32+lane (32..47), lane<=15

    // ---- consume the prefetched colors
    float4 acc = make_float4(0.f, 0.f, 0.f, 0.f);
    #pragma unroll
    for (int k = 0; k < 8; k++) {                    // s = 4k+g in 0..31
        float u = __shfl_sync(FULL, uA, 4 * k + g);
        acc.x = fmaf(u, c[k].x, acc.x);
        acc.y = fmaf(u, c[k].y, acc.y);
        acc.z = fmaf(u, c[k].z, acc.z);
        acc.w = fmaf(u, c[k].w, acc.w);
    }
    #pragma unroll
    for (int k = 8; k < 12; k++) {                   // s = 4k+g in 32..47
        float u = __shfl_sync(FULL, uB, 4 * k + g - 32);
        acc.x = fmaf(u, c[k].x, acc.x);
        acc.y = fmaf(u, c[k].y, acc.y);
        acc.z = fmaf(u, c[k].z, acc.z);
        acc.w = fmaf(u, c[k].w, acc.w);
    }

    // reduce across the 4 sample groups (xor 8, xor 16)
    #pragma unroll
    for (int off = 8; off <= 16; off <<= 1) {
        acc.x += __shfl_xor_sync(FULL, acc.x, off);
        acc.y += __shfl_xor_sync(FULL, acc.y, off);
        acc.z += __shfl_xor_sync(FULL, acc.z, off);
        acc.w += __shfl_xor_sync(FULL, acc.w, off);
    }

    // ---- rgb store
    if (g == 0) {  // lanes 0..7 hold the full sums for channel blocks 0..7
        float4 o;
        o.x = fmaf(acc.x, 2.0f, -1.0f);
        o.y = fmaf(acc.y, 2.0f, -1.0f);
        o.z = fmaf(acc.z, 2.0f, -1.0f);
        o.w = fmaf(acc.w, 2.0f, -1.0f);
        ((float4*)(out_rgb + ray * NC))[c4] = o;
    }
}

extern "C" void kernel_launch(void* const* d_in, const int* in_sizes, int n_in,
                              void* d_out, int out_size) {
    const float* colors    = (const float*)d_in[0];
    const float* densities = (const float*)d_in[1];
    const float* depths    = (const float*)d_in[2];

    const int n_rays = in_sizes[1] / NS;   // densities has B*R*S elements

    float* out       = (float*)d_out;
    float* out_rgb   = out;                       // n_rays * NC
    float* out_depth = out + (size_t)n_rays * NC; // n_rays
    float* out_w     = out_depth + n_rays;        // n_rays * NI

    const int threads = 128;                      // 4 warps/block
    const int warps_per_block = threads / 32;
    const int blocks = (n_rays + warps_per_block - 1) / warps_per_block;
    march_kernel<<<blocks, threads>>>(colors, densities, depths,
                                      out_rgb, out_depth, out_w, n_rays);
}

// round 13
// speedup vs baseline: 1.0005x; 1.0005x over previous
#include <cuda_runtime.h>

// Problem constants (fixed by the dataset): B=4, R=16384, S=48, C=32
#define NS 48      // samples per ray
#define NC 32      // channels
#define NI 47      // intervals = NS-1
#define FULL 0xffffffffu

// FINAL FORM (converged at the effective HBM roofline: ~6.76 TB/s, 85% of
// spec, traffic exactly minimal at 448.6 MB). One warp per ray, 4 warps/CTA.
//
// Interval math parallelized across lanes:
//   lane l owns interval l (chunk A) and interval 32+l for l<15 (chunk B).
// Transmittance cumprod -> warp shuffle product scan.
// Color compositing rewritten as sum_s c_s * u_s, u_s = 0.5*(w_{s-1}+w_s).
// All 12 float4 color loads are issued UP FRONT so their DRAM latency is
// hidden under the softplus/scan/shuffle phase (MLP~12 per thread).
// Stores stay in the tail: CTA churn overlaps them with other warps' loads
// (early-store variant measured worse; persistent grid-stride much worse).
//
// Depth clip note: reference clips composite_depth to [min(depths), max(depths)]
// over the WHOLE tensor. Per ray, d = sum(w*dmid)/sum(w) is a convex combination
// of midpoints strictly inside this ray's [dp0, dp_{NS-1}], which is inside the
// global range — so the clip is an identity whenever wsum > 0, which is
// guaranteed for this data. We clamp to the ray-local bounds, which yields the
// identical result without a global reduction.
__global__ void __launch_bounds__(128)
march_kernel(const float* __restrict__ colors,
             const float* __restrict__ densities,
             const float* __restrict__ depths,
             float* __restrict__ out_rgb,     // [n_rays, NC]
             float* __restrict__ out_depth,   // [n_rays]
             float* __restrict__ out_w,       // [n_rays, NI]
             int n_rays)
{
    const int warp = (blockIdx.x * blockDim.x + threadIdx.x) >> 5;
    const int lane = threadIdx.x & 31;
    if (warp >= n_rays) return;

    const size_t ray = (size_t)warp;
    const float* __restrict__ dn = densities + ray * NS;
    const float* __restrict__ dp = depths + ray * NS;

    // ---- scalar samples first (needed soonest)
    float denA = __ldg(dn + lane);
    float depA = __ldg(dp + lane);
    float denB = 0.0f, depB = 0.0f;
    if (lane < 16) {
        denB = __ldg(dn + 32 + lane);
        depB = __ldg(dp + 32 + lane);
    }

    // ---- issue ALL color loads now; consumed only after the scan phase.
    // lane -> (sample group g = lane>>3, channel block c4 = lane&7);
    // batch k covers sample s = 4k+g.
    const int g  = lane >> 3;
    const int c4 = lane & 7;
    const float4* __restrict__ cp = (const float4*)(colors + ray * (NS * NC));
    float4 c[12];
    #pragma unroll
    for (int k = 0; k < 12; k++)
        c[k] = __ldg(&cp[(4 * k + g) * 8 + c4]);

    // ---- neighbor (sample s+1) values
    float denA1 = __shfl_down_sync(FULL, denA, 1);   // sample lane+1 (lane<31)
    float depA1 = __shfl_down_sync(FULL, depA, 1);
    float denB0 = __shfl_sync(FULL, denB, 0);        // sample 32
    float depB0 = __shfl_sync(FULL, depB, 0);
    if (lane == 31) { denA1 = denB0; depA1 = depB0; }
    float denB1 = __shfl_down_sync(FULL, denB, 1);   // sample 33+lane (lane<15)
    float depB1 = __shfl_down_sync(FULL, depB, 1);

    // ray-local depth bounds (sorted): dp0 = sample 0, dpN = sample NS-1
    float dp0 = __shfl_sync(FULL, depA, 0);
    float dpN = __shfl_sync(FULL, depB, 15);

    // ---- per-interval alpha / v  (chunk A: i = lane, valid since NI=47>31)
    float deltaA = depA1 - depA;
    float dmidA  = 0.5f * (depA1 + depA);
    float smidA  = 0.5f * (denA1 + denA) - 1.0f;
    float spA    = log1pf(expf(smidA));
    float alphaA = 1.0f - expf(-spA * deltaA);
    float vA     = 1.0f - alphaA + 1e-10f;

    // chunk B: i = 32+lane, valid for lane < 15
    float alphaB = 0.0f, dmidB = 0.0f, vB = 1.0f;
    if (lane < 15) {
        float deltaB = depB1 - depB;
        dmidB  = 0.5f * (depB1 + depB);
        float smidB = 0.5f * (denB1 + denB) - 1.0f;
        float spB   = log1pf(expf(smidB));
        alphaB = 1.0f - expf(-spB * deltaB);
        vB     = 1.0f - alphaB + 1e-10f;
    }

    // ---- inclusive product scan of vA (full 32 lanes)
    float p = vA;
    #pragma unroll
    for (int off = 1; off < 32; off <<= 1) {
        float t = __shfl_up_sync(FULL, p, off);
        if (lane >= off) p *= t;
    }
    float TexA = __shfl_up_sync(FULL, p, 1);
    if (lane == 0) TexA = 1.0f;
    float wA = alphaA * TexA;
    float TtotA = __shfl_sync(FULL, p, 31);

    // ---- scan of vB: only prefixes over 15 elements are consumed,
    // so 4 steps (off=1,2,4,8) suffice.
    float q = vB;
    #pragma unroll
    for (int off = 1; off < 16; off <<= 1) {
        float t = __shfl_up_sync(FULL, q, off);
        if (lane >= off) q *= t;
    }
    float TexB = __shfl_up_sync(FULL, q, 1);
    if (lane == 0) TexB = 1.0f;
    float wB = alphaB * (TtotA * TexB);   // zero for lane >= 15

    // ---- wsum / dsum reductions (butterfly)
    float wsum = wA + wB;
    float dsum = wA * dmidA + wB * dmidB;
    #pragma unroll
    for (int off = 16; off >= 1; off >>= 1) {
        wsum += __shfl_xor_sync(FULL, wsum, off);
        dsum += __shfl_xor_sync(FULL, dsum, off);
    }

    // ---- u_s = 0.5*(w_{s-1} + w_s)
    float wAm1 = __shfl_up_sync(FULL, wA, 1);        // w_{lane-1}
    if (lane == 0) wAm1 = 0.0f;
    float uA = 0.5f * (wAm1 + wA);                   // s = lane (0..31)
    float wBm1 = __shfl_up_sync(FULL, wB, 1);        // w_{31+lane} for lane>=1
    float wA31 = __shfl_sync(FULL, wA, 31);
    if (lane == 0) wBm1 = wA31;                      // w_31
    float uB = 0.5f * (wBm1 + wB);                   // s = 32+lane (32..47), lane<=15

    // ---- consume the prefetched colors
    float4 acc = make_float4(0.f, 0.f, 0.f, 0.f);
    #pragma unroll
    for (int k = 0; k < 8; k++) {                    // s = 4k+g in 0..31
        float u = __shfl_sync(FULL, uA, 4 * k + g);
        acc.x = fmaf(u, c[k].x, acc.x);
        acc.y = fmaf(u, c[k].y, acc.y);
        acc.z = fmaf(u, c[k].z, acc.z);
        acc.w = fmaf(u, c[k].w, acc.w);
    }
    #pragma unroll
    for (int k = 8; k < 12; k++) {                   // s = 4k+g in 32..47
        float u = __shfl_sync(FULL, uB, 4 * k + g - 32);
        acc.x = fmaf(u, c[k].x, acc.x);
        acc.y = fmaf(u, c[k].y, acc.y);
        acc.z = fmaf(u, c[k].z, acc.z);
        acc.w = fmaf(u, c[k].w, acc.w);
    }

    // reduce across the 4 sample groups (xor 8, xor 16)
    #pragma unroll
    for (int off = 8; off <= 16; off <<= 1) {
        acc.x += __shfl_xor_sync(FULL, acc.x, off);
        acc.y += __shfl_xor_sync(FULL, acc.y, off);
        acc.z += __shfl_xor_sync(FULL, acc.z, off);
        acc.w += __shfl_xor_sync(FULL, acc.w, off);
    }

    // ---- stores
    if (g == 0) {  // lanes 0..7 hold the full sums for channel blocks 0..7
        float4 o;
        o.x = fmaf(acc.x, 2.0f, -1.0f);
        o.y = fmaf(acc.y, 2.0f, -1.0f);
        o.z = fmaf(acc.z, 2.0f, -1.0f);
        o.w = fmaf(acc.w, 2.0f, -1.0f);
        ((float4*)(out_rgb + ray * NC))[c4] = o;
    }

    out_w[ray * NI + lane] = wA;                     // i = 0..31
    if (lane < 15)
        out_w[ray * NI + 32 + lane] = wB;            // i = 32..46

    if (lane == 0) {
        float d = dsum / wsum;
        // wsum > 0 is guaranteed for this data; clamp to ray-local bounds,
        // which equals the reference's global clip (see comment above).
        if (!(d == d)) d = dpN;                      // defensive nan -> upper bound
        d = fminf(d, dpN);
        d = fmaxf(d, dp0);
        out_depth[ray] = d;
    }
}

extern "C" void kernel_launch(void* const* d_in, const int* in_sizes, int n_in,
                              void* d_out, int out_size) {
    const float* colors    = (const float*)d_in[0];
    const float* densities = (const float*)d_in[1];
    const float* depths    = (const float*)d_in[2];

    const int n_rays = in_sizes[1] / NS;   // densities has B*R*S elements

    float* out       = (float*)d_out;
    float* out_rgb   = out;                       // n_rays * NC
    float* out_depth = out + (size_t)n_rays * NC; // n_rays
    float* out_w     = out_depth + n_rays;        // n_rays * NI

    const int threads = 128;                      // 4 warps/block
    const int warps_per_block = threads / 32;
    const int blocks = (n_rays + warps_per_block - 1) / warps_per_block;
    march_kernel<<<blocks, threads>>>(colors, densities, depths,
                                      out_rgb, out_depth, out_w, n_rays);
}

// round 14
// speedup vs baseline: 1.0042x; 1.0038x over previous
#include <cuda_runtime.h>

// Problem constants (fixed by the dataset): B=4, R=16384, S=48, C=32
#define NS 48      // samples per ray
#define NC 32      // channels
#define NI 47      // intervals = NS-1
#define FULL 0xffffffffu

// FINAL FORM (converged at the effective HBM roofline: ~6.76 TB/s, 85% of
// spec, traffic exactly minimal at 448.6 MB). One warp per ray, 4 warps/CTA.
// All healthy variants (block {64,128,256}, reg/SMEM staging, occupancy
// caps, persistence, store order) measured within a 0.4% total band; this
// configuration has the fastest ncu-measured kernel time (66.2us, 85.3% DRAM).
//
// Interval math parallelized across lanes:
//   lane l owns interval l (chunk A) and interval 32+l for l<15 (chunk B).
// Transmittance cumprod -> warp shuffle product scan.
// Color compositing rewritten as sum_s c_s * u_s, u_s = 0.5*(w_{s-1}+w_s).
// All 12 float4 color loads are issued UP FRONT so their DRAM latency is
// hidden under the softplus/scan/shuffle phase (MLP~12 per thread).
// Stores stay in the tail: CTA churn overlaps them with other warps' loads
// (early-store variant measured worse; persistent grid-stride much worse).
//
// Depth clip note: reference clips composite_depth to [min(depths), max(depths)]
// over the WHOLE tensor. Per ray, d = sum(w*dmid)/sum(w) is a convex combination
// of midpoints strictly inside this ray's [dp0, dp_{NS-1}], which is inside the
// global range — so the clip is an identity whenever wsum > 0, which is
// guaranteed for this data. We clamp to the ray-local bounds, which yields the
// identical result without a global reduction.
__global__ void __launch_bounds__(128)
march_kernel(const float* __restrict__ colors,
             const float* __restrict__ densities,
             const float* __restrict__ depths,
             float* __restrict__ out_rgb,     // [n_rays, NC]
             float* __restrict__ out_depth,   // [n_rays]
             float* __restrict__ out_w,       // [n_rays, NI]
             int n_rays)
{
    const int warp = (blockIdx.x * blockDim.x + threadIdx.x) >> 5;
    const int lane = threadIdx.x & 31;
    if (warp >= n_rays) return;

    const size_t ray = (size_t)warp;
    const float* __restrict__ dn = densities + ray * NS;
    const float* __restrict__ dp = depths + ray * NS;

    // ---- scalar samples first (needed soonest)
    float denA = __ldg(dn + lane);
    float depA = __ldg(dp + lane);
    float denB = 0.0f, depB = 0.0f;
    if (lane < 16) {
        denB = __ldg(dn + 32 + lane);
        depB = __ldg(dp + 32 + lane);
    }

    // ---- issue ALL color loads now; consumed only after the scan phase.
    // lane -> (sample group g = lane>>3, channel block c4 = lane&7);
    // batch k covers sample s = 4k+g.
    const int g  = lane >> 3;
    const int c4 = lane & 7;
    const float4* __restrict__ cp = (const float4*)(colors + ray * (NS * NC));
    float4 c[12];
    #pragma unroll
    for (int k = 0; k < 12; k++)
        c[k] = __ldg(&cp[(4 * k + g) * 8 + c4]);

    // ---- neighbor (sample s+1) values
    float denA1 = __shfl_down_sync(FULL, denA, 1);   // sample lane+1 (lane<31)
    float depA1 = __shfl_down_sync(FULL, depA, 1);
    float denB0 = __shfl_sync(FULL, denB, 0);        // sample 32
    float depB0 = __shfl_sync(FULL, depB, 0);
    if (lane == 31) { denA1 = denB0; depA1 = depB0; }
    float denB1 = __shfl_down_sync(FULL, denB, 1);   // sample 33+lane (lane<15)
    float depB1 = __shfl_down_sync(FULL, depB, 1);

    // ray-local depth bounds (sorted): dp0 = sample 0, dpN = sample NS-1
    float dp0 = __shfl_sync(FULL, depA, 0);
    float dpN = __shfl_sync(FULL, depB, 15);

    // ---- per-interval alpha / v  (chunk A: i = lane, valid since NI=47>31)
    float deltaA = depA1 - depA;
    float dmidA  = 0.5f * (depA1 + depA);
    float smidA  = 0.5f * (denA1 + denA) - 1.0f;
    float spA    = log1pf(expf(smidA));
    float alphaA = 1.0f - expf(-spA * deltaA);
    float vA     = 1.0f - alphaA + 1e-10f;

    // chunk B: i = 32+lane, valid for lane < 15
    float alphaB = 0.0f, dmidB = 0.0f, vB = 1.0f;
    if (lane < 15) {
        float deltaB = depB1 - depB;
        dmidB  = 0.5f * (depB1 + depB);
        float smidB = 0.5f * (denB1 + denB) - 1.0f;
        float spB   = log1pf(expf(smidB));
        alphaB = 1.0f - expf(-spB * deltaB);
        vB     = 1.0f - alphaB + 1e-10f;
    }

    // ---- inclusive product scan of vA (full 32 lanes)
    float p = vA;
    #pragma unroll
    for (int off = 1; off < 32; off <<= 1) {
        float t = __shfl_up_sync(FULL, p, off);
        if (lane >= off) p *= t;
    }
    float TexA = __shfl_up_sync(FULL, p, 1);
    if (lane == 0) TexA = 1.0f;
    float wA = alphaA * TexA;
    float TtotA = __shfl_sync(FULL, p, 31);

    // ---- scan of vB: only prefixes over 15 elements are consumed,
    // so 4 steps (off=1,2,4,8) suffice.
    float q = vB;
    #pragma unroll
    for (int off = 1; off < 16; off <<= 1) {
        float t = __shfl_up_sync(FULL, q, off);
        if (lane >= off) q *= t;
    }
    float TexB = __shfl_up_sync(FULL, q, 1);
    if (lane == 0) TexB = 1.0f;
    float wB = alphaB * (TtotA * TexB);   // zero for lane >= 15

    // ---- wsum / dsum reductions (butterfly)
    float wsum = wA + wB;
    float dsum = wA * dmidA + wB * dmidB;
    #pragma unroll
    for (int off = 16; off >= 1; off >>= 1) {
        wsum += __shfl_xor_sync(FULL, wsum, off);
        dsum += __shfl_xor_sync(FULL, dsum, off);
    }

    // ---- u_s = 0.5*(w_{s-1} + w_s)
    float wAm1 = __shfl_up_sync(FULL, wA, 1);        // w_{lane-1}
    if (lane == 0) wAm1 = 0.0f;
    float uA = 0.5f * (wAm1 + wA);                   // s = lane (0..31)
    float wBm1 = __shfl_up_sync(FULL, wB, 1);        // w_{31+lane} for lane>=1
    float wA31 = __shfl_sync(FULL, wA, 31);
    if (lane == 0) wBm1 = wA31;                      // w_31
    float uB = 0.5f * (wBm1 + wB);                   // s = 32+lane (32..47), lane<=15

    // ---- consume the prefetched colors
    float4 acc = make_float4(0.f, 0.f, 0.f, 0.f);
    #pragma unroll
    for (int k = 0; k < 8; k++) {                    // s = 4k+g in 0..31
        float u = __shfl_sync(FULL, uA, 4 * k + g);
        acc.x = fmaf(u, c[k].x, acc.x);
        acc.y = fmaf(u, c[k].y, acc.y);
        acc.z = fmaf(u, c[k].z, acc.z);
        acc.w = fmaf(u, c[k].w, acc.w);
    }
    #pragma unroll
    for (int k = 8; k < 12; k++) {                   // s = 4k+g in 32..47
        float u = __shfl_sync(FULL, uB, 4 * k + g - 32);
        acc.x = fmaf(u, c[k].x, acc.x);
        acc.y = fmaf(u, c[k].y, acc.y);
        acc.z = fmaf(u, c[k].z, acc.z);
        acc.w = fmaf(u, c[k].w, acc.w);
    }

    // reduce across the 4 sample groups (xor 8, xor 16)
    #pragma unroll
    for (int off = 8; off <= 16; off <<= 1) {
        acc.x += __shfl_xor_sync(FULL, acc.x, off);
        acc.y += __shfl_xor_sync(FULL, acc.y, off);
        acc.z += __shfl_xor_sync(FULL, acc.z, off);
        acc.w += __shfl_xor_sync(FULL, acc.w, off);
    }

    // ---- stores
    if (g == 0) {  // lanes 0..7 hold the full sums for channel blocks 0..7
        float4 o;
        o.x = fmaf(acc.x, 2.0f, -1.0f);
        o.y = fmaf(acc.y, 2.0f, -1.0f);
        o.z = fmaf(acc.z, 2.0f, -1.0f);
        o.w = fmaf(acc.w, 2.0f, -1.0f);
        ((float4*)(out_rgb + ray * NC))[c4] = o;
    }

    out_w[ray * NI + lane] = wA;                     // i = 0..31
    if (lane < 15)
        out_w[ray * NI + 32 + lane] = wB;            // i = 32..46

    if (lane == 0) {
        float d = dsum / wsum;
        // wsum > 0 is guaranteed for this data; clamp to ray-local bounds,
        // which equals the reference's global clip (see comment above).
        if (!(d == d)) d = dpN;                      // defensive nan -> upper bound
        d = fminf(d, dpN);
        d = fmaxf(d, dp0);
        out_depth[ray] = d;
    }
}

extern "C" void kernel_launch(void* const* d_in, const int* in_sizes, int n_in,
                              void* d_out, int out_size) {
    const float* colors    = (const float*)d_in[0];
    const float* densities = (const float*)d_in[1];
    const float* depths    = (const float*)d_in[2];

    const int n_rays = in_sizes[1] / NS;   // densities has B*R*S elements

    float* out       = (float*)d_out;
    float* out_rgb   = out;                       // n_rays * NC
    float* out_depth = out + (size_t)n_rays * NC; // n_rays
    float* out_w     = out_depth + n_rays;        // n_rays * NI

    const int threads = 128;                      // 4 warps/block
    const int warps_per_block = threads / 32;
    const int blocks = (n_rays + warps_per_block - 1) / warps_per_block;
    march_kernel<<<blocks, threads>>>(colors, densities, depths,
                                      out_rgb, out_depth, out_w, n_rays);
}